// round 16
// baseline (speedup 1.0000x reference)
#include <cuda_runtime.h>
#include <math.h>

#define NLEV 16
#define MAX_SIZE (1u << 19)
#define P1 2654435761u
#define P2 805459861u

#define NPTS_MAX 2097152
#define KEY_BITS_DIM 6                   // res-64 Morton key
#define KEY_BITS (3 * KEY_BITS_DIM)      // 18
#define NBINS (1u << KEY_BITS)           // 262144 bins, ~8 pts/bin
#define SCAN_BLK 2048
#define NSCANBLKS (NBINS / SCAN_BLK)     // 128

struct LP {
    float    res[NLEV];
    unsigned mask[NLEV];
};

// Static scratch (allocation-free rule: __device__ globals)
__device__ unsigned d_hist[NBINS];       // becomes intra-block exclusive scan
__device__ unsigned d_bsums[NSCANBLKS];  // exclusive scan of block sums
__device__ unsigned d_packed[NPTS_MAX];  // (rank << 18) | key per point
__device__ unsigned d_perm[NPTS_MAX];    // sorted slot -> original point index

// ---------------- Morton key (6 bits/dim -> 18-bit key) ----------------
__device__ __forceinline__ unsigned expand_bits(unsigned v)
{
    v = (v | (v << 16)) & 0x030000FFu;
    v = (v | (v << 8))  & 0x0300F00Fu;
    v = (v | (v << 4))  & 0x030C30C3u;
    v = (v | (v << 2))  & 0x09249249u;
    return v;
}
__device__ __forceinline__ unsigned morton_key(float px, float py, float pz)
{
    unsigned ix = min(63u, (unsigned)(px * 64.0f));
    unsigned iy = min(63u, (unsigned)(py * 64.0f));
    unsigned iz = min(63u, (unsigned)(pz * 64.0f));
    return expand_bits(ix) | (expand_bits(iy) << 1) | (expand_bits(iz) << 2);
}

// ---------------- Sort pipeline ----------------
__global__ void k_hist(const float* __restrict__ x, int n)
{
    int i = blockIdx.x * blockDim.x + threadIdx.x;
    if (i >= n) return;
    unsigned k = morton_key(x[3 * i], x[3 * i + 1], x[3 * i + 2]);
    unsigned r = atomicAdd(&d_hist[k], 1u);
    d_packed[i] = (r << KEY_BITS) | k;
}

__global__ void __launch_bounds__(1024) k_scan1()
{
    __shared__ unsigned s[SCAN_BLK];
    const int t = threadIdx.x;
    const unsigned base = blockIdx.x * SCAN_BLK;
    s[t] = d_hist[base + t];
    s[t + 1024] = d_hist[base + t + 1024];
    int offset = 1;
    for (int d = SCAN_BLK >> 1; d > 0; d >>= 1) {
        __syncthreads();
        if (t < d) {
            int ai = offset * (2 * t + 1) - 1;
            int bi = offset * (2 * t + 2) - 1;
            s[bi] += s[ai];
        }
        offset <<= 1;
    }
    if (t == 0) { d_bsums[blockIdx.x] = s[SCAN_BLK - 1]; s[SCAN_BLK - 1] = 0; }
    for (int d = 1; d < SCAN_BLK; d <<= 1) {
        offset >>= 1;
        __syncthreads();
        if (t < d) {
            int ai = offset * (2 * t + 1) - 1;
            int bi = offset * (2 * t + 2) - 1;
            unsigned tm = s[ai]; s[ai] = s[bi]; s[bi] += tm;
        }
    }
    __syncthreads();
    d_hist[base + t] = s[t];
    d_hist[base + t + 1024] = s[t + 1024];
}

__global__ void __launch_bounds__(128) k_scan2()
{
    __shared__ unsigned s[NSCANBLKS];
    const int t = threadIdx.x;
    s[t] = d_bsums[t];
    __syncthreads();
    unsigned v = s[t];
    for (int d = 1; d < NSCANBLKS; d <<= 1) {
        unsigned add = (t >= d) ? s[t - d] : 0u;
        __syncthreads();
        v += add;
        s[t] = v;
        __syncthreads();
    }
    d_bsums[t] = (t == 0) ? 0u : s[t - 1];
}

__global__ void k_scatter(int n)
{
    int i = blockIdx.x * blockDim.x + threadIdx.x;
    if (i >= n) return;
    const unsigned pk = d_packed[i];
    const unsigned k  = pk & (NBINS - 1u);
    const unsigned r  = pk >> KEY_BITS;
    d_perm[d_hist[k] + d_bsums[k >> 11] + r] = (unsigned)i;
}

// ---------------- Encode: 2 lanes/point, 16 points/warp, lane = bx ----------------
// Templated over level range and ordering. SORTED=false processes points in
// original order (coalesced x loads, no perm) — correct for fine levels where
// sorting gives no sharing. Each lane keeps NLV/2 levels = NLV floats.
template<int LBEG, int NLV, int FOFF, bool SORTED>
__global__ void __launch_bounds__(256)
enc_kernel(const float* __restrict__ x,
           const float* __restrict__ tables,
           float* __restrict__ out,
           LP lp, int n)
{
    const int lane   = threadIdx.x & 31;
    const int warpid = (blockIdx.x * (blockDim.x >> 5)) + (threadIdx.x >> 5);
    const int ptraw  = warpid * 16 + (lane >> 1);
    const bool valid = ptraw < n;
    const int pt     = valid ? ptraw : (n - 1);   // clamp; lanes stay converged
    const unsigned p = lane & 1;                  // bx for this lane

    const unsigned oidx = SORTED ? __ldg(&d_perm[pt]) : (unsigned)pt;
    const float px = __ldg(&x[3 * oidx + 0]);
    const float py = __ldg(&x[3 * oidx + 1]);
    const float pz = __ldg(&x[3 * oidx + 2]);

    float rf[NLV];   // lane p keeps levels li in [ (NLV/2)*p, (NLV/2)*(p+1) )

#pragma unroll
    for (int li = 0; li < NLV; ++li) {
        const int l = LBEG + li;
        const float    res  = lp.res[l];
        const unsigned mask = lp.mask[l];
        const float2* __restrict__ tbl =
            reinterpret_cast<const float2*>(tables) + (size_t)l * MAX_SIZE;

        const float xs = px * res, ys = py * res, zs = pz * res;
        const float fx = floorf(xs), fy = floorf(ys), fz = floorf(zs);

        const unsigned ix = (unsigned)fx + p;
        const unsigned iy = (unsigned)fy;
        const unsigned iz = (unsigned)fz;

        const float xf = xs - fx, yf = ys - fy, zf = zs - fz;
        const float wx   = p ? xf : (1.0f - xf);
        const float wy0  = 1.0f - yf, wy1 = yf;
        const float wz0  = 1.0f - zf, wz1 = zf;
        const float w00  = wy0 * wz0;
        const float w10  = wy1 * wz0;
        const float w01  = wy0 * wz1;
        const float w11  = wy1 * wz1;

        const unsigned hy0 = iy * P1;
        const unsigned hy1 = hy0 + P1;
        const unsigned hz0 = iz * P2;
        const unsigned hz1 = hz0 + P2;

        const unsigned h00 = (ix ^ hy0 ^ hz0) & mask;
        const unsigned h10 = (ix ^ hy1 ^ hz0) & mask;
        const unsigned h01 = (ix ^ hy0 ^ hz1) & mask;
        const unsigned h11 = (ix ^ hy1 ^ hz1) & mask;

        const float2 f00 = __ldg(&tbl[h00]);
        const float2 f10 = __ldg(&tbl[h10]);
        const float2 f01 = __ldg(&tbl[h01]);
        const float2 f11 = __ldg(&tbl[h11]);

        float ax = w00 * f00.x;
        float ay = w00 * f00.y;
        ax = fmaf(w10, f10.x, ax);
        ay = fmaf(w10, f10.y, ay);
        ax = fmaf(w01, f01.x, ax);
        ay = fmaf(w01, f01.y, ay);
        ax = fmaf(w11, f11.x, ax);
        ay = fmaf(w11, f11.y, ay);

        float vx = wx * ax;
        float vy = wx * ay;

        // sum the two x-halves
        vx += __shfl_xor_sync(0xffffffffu, vx, 1);
        vy += __shfl_xor_sync(0xffffffffu, vy, 1);

        if ((li / (NLV / 2)) == (int)p) {
            rf[2 * (li % (NLV / 2)) + 0] = vx;
            rf[2 * (li % (NLV / 2)) + 1] = vy;
        }
    }

    if (valid) {
        float* base = out + (size_t)oidx * 32 + FOFF + NLV * p;
#pragma unroll
        for (int k = 0; k < NLV / 4; ++k)
            reinterpret_cast<float4*>(base)[k] =
                make_float4(rf[4 * k], rf[4 * k + 1], rf[4 * k + 2], rf[4 * k + 3]);
    }
}

extern "C" void kernel_launch(void* const* d_in, const int* in_sizes, int n_in,
                              void* d_out, int out_size)
{
    const float* x      = (const float*)d_in[0];
    const float* tables = (const float*)d_in[1];
    float*       out    = (float*)d_out;
    const int    n      = in_sizes[0] / 3;

    // Replicate the reference's level-resolution math EXACTLY in double precision.
    LP lp;
    const double b = exp((log(512.0) - log(16.0)) / 15.0);
    for (int l = 0; l < NLEV; ++l) {
        const double r   = floor(16.0 * pow(b, (double)l));
        const long   res = (long)r;
        long sz = res * res * res;
        if (sz > (1L << 19)) sz = (1L << 19);
        long p = 1;
        while (p < sz) p <<= 1;
        lp.res[l]  = (float)r;
        lp.mask[l] = (unsigned)(p - 1);
    }

    static void* hist_ptr = nullptr;
    static cudaStream_t sPipe = nullptr;
    static cudaEvent_t  evFork = nullptr, evJoin = nullptr;
    if (!hist_ptr) {
        cudaGetSymbolAddress(&hist_ptr, d_hist);
        cudaStreamCreateWithFlags(&sPipe, cudaStreamNonBlocking);
        cudaEventCreateWithFlags(&evFork, cudaEventDisableTiming);
        cudaEventCreateWithFlags(&evJoin, cudaEventDisableTiming);
    }

    const int threads = 256;
    const int pts_per_block = (threads / 32) * 16;     // 128
    const int eblocks = (n + pts_per_block - 1) / pts_per_block;

    // Fork: side stream carries the sort pipeline, concurrent with enc_fine.
    cudaEventRecord(evFork, 0);
    cudaStreamWaitEvent(sPipe, evFork, 0);

    // Main stream: fine levels (l8..15) in ORIGINAL order — no sort needed.
    enc_kernel<8, 8, 16, false><<<eblocks, threads>>>(x, tables, out, lp, n);

    // Side stream: memset -> hist -> scan -> scatter.
    cudaMemsetAsync(hist_ptr, 0, NBINS * sizeof(unsigned), sPipe);
    k_hist<<<(n + 255) / 256, 256, 0, sPipe>>>(x, n);
    k_scan1<<<NSCANBLKS, 1024, 0, sPipe>>>();
    k_scan2<<<1, 128, 0, sPipe>>>();
    k_scatter<<<(n + 255) / 256, 256, 0, sPipe>>>(n);
    cudaEventRecord(evJoin, sPipe);

    // Join: coarse levels (l0..7) in sorted order after perm is ready.
    cudaStreamWaitEvent(0, evJoin, 0);
    enc_kernel<0, 8, 0, true><<<eblocks, threads>>>(x, tables, out, lp, n);
}

// round 17
// speedup vs baseline: 1.3780x; 1.3780x over previous
#include <cuda_runtime.h>
#include <math.h>

#define NLEV 16
#define MAX_SIZE (1u << 19)
#define P1 2654435761u
#define P2 805459861u

#define NPTS_MAX 2097152
#define KEY_BITS_DIM 6                   // res-64 Morton key
#define KEY_BITS (3 * KEY_BITS_DIM)      // 18
#define NBINS (1u << KEY_BITS)           // 262144 bins, ~8 pts/bin
#define SCAN_BLK 2048
#define NSCANBLKS (NBINS / SCAN_BLK)     // 128

struct LP {
    float    res[NLEV];
    unsigned mask[NLEV];
};

// Static scratch (allocation-free rule: __device__ globals)
__device__ unsigned d_hist[NBINS];       // bin counts; RE-ZEROED by k_scan1 (no memset node)
__device__ unsigned d_scan[NBINS];       // intra-block exclusive scan output
__device__ unsigned d_bsums[NSCANBLKS];  // block sums -> exclusive scan (by last block)
__device__ unsigned d_packed[NPTS_MAX];  // (rank << 18) | key per point
__device__ unsigned d_perm[NPTS_MAX];    // sorted slot -> original point index
__device__ unsigned d_ticket;            // last-block ticket (reset each run)

// ---------------- Morton key (6 bits/dim -> 18-bit key) ----------------
__device__ __forceinline__ unsigned expand_bits(unsigned v)
{
    v = (v | (v << 16)) & 0x030000FFu;
    v = (v | (v << 8))  & 0x0300F00Fu;
    v = (v | (v << 4))  & 0x030C30C3u;
    v = (v | (v << 2))  & 0x09249249u;
    return v;
}
__device__ __forceinline__ unsigned morton_key(float px, float py, float pz)
{
    unsigned ix = min(63u, (unsigned)(px * 64.0f));
    unsigned iy = min(63u, (unsigned)(py * 64.0f));
    unsigned iz = min(63u, (unsigned)(pz * 64.0f));
    return expand_bits(ix) | (expand_bits(iy) << 1) | (expand_bits(iz) << 2);
}

// ---------------- Sort pipeline ----------------
__global__ void k_hist(const float* __restrict__ x, int n)
{
    int i = blockIdx.x * blockDim.x + threadIdx.x;
    if (i >= n) return;
    unsigned k = morton_key(x[3 * i], x[3 * i + 1], x[3 * i + 2]);
    unsigned r = atomicAdd(&d_hist[k], 1u);
    d_packed[i] = (r << KEY_BITS) | k;
}

// Blelloch scan of d_hist per 2048-bin block into d_scan; d_hist re-zeroed.
// The LAST block to finish additionally scans d_bsums (fused k_scan2) and
// resets the ticket so every graph replay starts clean.
__global__ void __launch_bounds__(1024) k_scan1()
{
    __shared__ unsigned s[SCAN_BLK];
    const int t = threadIdx.x;
    const unsigned base = blockIdx.x * SCAN_BLK;
    s[t] = d_hist[base + t];
    s[t + 1024] = d_hist[base + t + 1024];
    int offset = 1;
    for (int d = SCAN_BLK >> 1; d > 0; d >>= 1) {
        __syncthreads();
        if (t < d) {
            int ai = offset * (2 * t + 1) - 1;
            int bi = offset * (2 * t + 2) - 1;
            s[bi] += s[ai];
        }
        offset <<= 1;
    }
    if (t == 0) { d_bsums[blockIdx.x] = s[SCAN_BLK - 1]; s[SCAN_BLK - 1] = 0; }
    for (int d = 1; d < SCAN_BLK; d <<= 1) {
        offset >>= 1;
        __syncthreads();
        if (t < d) {
            int ai = offset * (2 * t + 1) - 1;
            int bi = offset * (2 * t + 2) - 1;
            unsigned tm = s[ai]; s[ai] = s[bi]; s[bi] += tm;
        }
    }
    __syncthreads();
    d_scan[base + t] = s[t];
    d_scan[base + t + 1024] = s[t + 1024];
    // re-zero the histogram for the next replay (replaces the memset node)
    d_hist[base + t] = 0u;
    d_hist[base + t + 1024] = 0u;

    // ---- fused bsums scan: last block through the ticket does it ----
    __shared__ unsigned is_last;
    if (t == 0) {
        __threadfence();                        // publish d_bsums write
        unsigned tk = atomicAdd(&d_ticket, 1u);
        is_last = (tk == NSCANBLKS - 1u) ? 1u : 0u;
    }
    __syncthreads();
    if (is_last) {
        __shared__ unsigned sb[NSCANBLKS];
        if (t < NSCANBLKS) sb[t] = d_bsums[t];
        __syncthreads();
        unsigned v = (t < NSCANBLKS) ? sb[t] : 0u;
        for (int d = 1; d < NSCANBLKS; d <<= 1) {
            unsigned add = (t >= d && t < NSCANBLKS) ? sb[t - d] : 0u;
            __syncthreads();
            if (t < NSCANBLKS) { v += add; sb[t] = v; }
            __syncthreads();
        }
        if (t < NSCANBLKS) d_bsums[t] = (t == 0) ? 0u : sb[t - 1];
        if (t == 0) d_ticket = 0u;              // reset for next replay
    }
}

// Atomic-free 4B scatter: slot = local_scan[k] + block_prefix + rank.
__global__ void k_scatter(int n)
{
    int i = blockIdx.x * blockDim.x + threadIdx.x;
    if (i >= n) return;
    const unsigned pk = d_packed[i];
    const unsigned k  = pk & (NBINS - 1u);
    const unsigned r  = pk >> KEY_BITS;
    d_perm[d_scan[k] + d_bsums[k >> 11] + r] = (unsigned)i;
}

// ---------------- Main encode: 2 lanes/point, 16 points/warp, lane = bx ----------------
// The two lanes of a point load hash indices differing by XOR(ix^(ix+1)) inside
// the SAME LDG instruction -> same 128B line 15/16 of the time -> the x-pair
// wavefront merges in hardware.
__global__ void __launch_bounds__(256)
hashgrid_kernel(const float* __restrict__ x,
                const float* __restrict__ tables,
                float* __restrict__ out,
                LP lp, int n)
{
    const int lane   = threadIdx.x & 31;
    const int warpid = (blockIdx.x * (blockDim.x >> 5)) + (threadIdx.x >> 5);
    const int ptraw  = warpid * 16 + (lane >> 1);
    const bool valid = ptraw < n;
    const int pt     = valid ? ptraw : (n - 1);   // clamp; lanes stay converged
    const unsigned p = lane & 1;                  // bx for this lane

    const unsigned oidx = __ldg(&d_perm[pt]);
    const float px = __ldg(&x[3 * oidx + 0]);
    const float py = __ldg(&x[3 * oidx + 1]);
    const float pz = __ldg(&x[3 * oidx + 2]);

    // Lane p keeps levels [8p, 8p+8): 8 float2 = 16 floats.
    float rf[16];

#pragma unroll
    for (int l = 0; l < NLEV; ++l) {
        const float    res  = lp.res[l];
        const unsigned mask = lp.mask[l];
        const float2* __restrict__ tbl =
            reinterpret_cast<const float2*>(tables) + (size_t)l * MAX_SIZE;

        const float xs = px * res, ys = py * res, zs = pz * res;
        const float fx = floorf(xs), fy = floorf(ys), fz = floorf(zs);

        const unsigned ix = (unsigned)fx + p;
        const unsigned iy = (unsigned)fy;
        const unsigned iz = (unsigned)fz;

        const float xf = xs - fx, yf = ys - fy, zf = zs - fz;
        const float wx   = p ? xf : (1.0f - xf);
        const float wy0  = 1.0f - yf, wy1 = yf;
        const float wz0  = 1.0f - zf, wz1 = zf;
        const float w00  = wy0 * wz0;
        const float w10  = wy1 * wz0;
        const float w01  = wy0 * wz1;
        const float w11  = wy1 * wz1;

        const unsigned hy0 = iy * P1;
        const unsigned hy1 = hy0 + P1;
        const unsigned hz0 = iz * P2;
        const unsigned hz1 = hz0 + P2;

        const unsigned h00 = (ix ^ hy0 ^ hz0) & mask;
        const unsigned h10 = (ix ^ hy1 ^ hz0) & mask;
        const unsigned h01 = (ix ^ hy0 ^ hz1) & mask;
        const unsigned h11 = (ix ^ hy1 ^ hz1) & mask;

        const float2 f00 = __ldg(&tbl[h00]);
        const float2 f10 = __ldg(&tbl[h10]);
        const float2 f01 = __ldg(&tbl[h01]);
        const float2 f11 = __ldg(&tbl[h11]);

        // accumulate over (by,bz), then scale once by wx
        float ax = w00 * f00.x;
        float ay = w00 * f00.y;
        ax = fmaf(w10, f10.x, ax);
        ay = fmaf(w10, f10.y, ay);
        ax = fmaf(w01, f01.x, ax);
        ay = fmaf(w01, f01.y, ay);
        ax = fmaf(w11, f11.x, ax);
        ay = fmaf(w11, f11.y, ay);

        float vx = wx * ax;
        float vy = wx * ay;

        // sum the two x-halves
        vx += __shfl_xor_sync(0xffffffffu, vx, 1);
        vy += __shfl_xor_sync(0xffffffffu, vy, 1);

        // lane p stashes levels 8p..8p+7
        if ((l >> 3) == (int)p) {
            rf[2 * (l & 7) + 0] = vx;
            rf[2 * (l & 7) + 1] = vy;
        }
    }

    if (valid) {
        float4* o = reinterpret_cast<float4*>(out + (size_t)oidx * 32) + 4 * p;
        o[0] = make_float4(rf[0],  rf[1],  rf[2],  rf[3]);
        o[1] = make_float4(rf[4],  rf[5],  rf[6],  rf[7]);
        o[2] = make_float4(rf[8],  rf[9],  rf[10], rf[11]);
        o[3] = make_float4(rf[12], rf[13], rf[14], rf[15]);
    }
}

extern "C" void kernel_launch(void* const* d_in, const int* in_sizes, int n_in,
                              void* d_out, int out_size)
{
    const float* x      = (const float*)d_in[0];
    const float* tables = (const float*)d_in[1];
    float*       out    = (float*)d_out;
    const int    n      = in_sizes[0] / 3;

    // Replicate the reference's level-resolution math EXACTLY in double precision.
    LP lp;
    const double b = exp((log(512.0) - log(16.0)) / 15.0);
    for (int l = 0; l < NLEV; ++l) {
        const double r   = floor(16.0 * pow(b, (double)l));
        const long   res = (long)r;
        long sz = res * res * res;
        if (sz > (1L << 19)) sz = (1L << 19);
        long p = 1;
        while (p < sz) p <<= 1;
        lp.res[l]  = (float)r;
        lp.mask[l] = (unsigned)(p - 1);
    }

    // 1) histogram; pack (rank, key) per point  (d_hist starts zero: zero-init
    //    at load, then re-zeroed by k_scan1 every run)
    k_hist<<<(n + 255) / 256, 256>>>(x, n);

    // 2) scan (+ fused bsums scan in last block; re-zeroes d_hist)
    k_scan1<<<NSCANBLKS, 1024>>>();

    // 3) atomic-free 4B perm scatter
    k_scatter<<<(n + 255) / 256, 256>>>(n);

    // 4) encode: 16 points per warp, 128 points per 256-thread block
    const int threads = 256;
    const int pts_per_block = (threads / 32) * 16;
    const int blocks = (n + pts_per_block - 1) / pts_per_block;
    hashgrid_kernel<<<blocks, threads>>>(x, tables, out, lp, n);
}